// round 11
// baseline (speedup 1.0000x reference)
#include <cuda_runtime.h>
#include <cuda_fp16.h>
#include <cstdint>

#define NN   50000
#define NE   800000
#define FF   500
#define NB   49          // (NN+1023)/1024 scan tiles
#define CSTF 1e-5f

// ---------------- scratch (static device globals; no allocation) ------------
__device__ float  g_x[(size_t)NN * 64];       // relu(node_feat@Wi+bi)
__device__ float  g_Q[(size_t)NN * 64];       // 1+elu(x@Wq+bq)   [n][h*16+i]
__device__ float  g_K[(size_t)NN * 64];       // 1+elu(x@Wk+bk)   [n][h*16+i]
__device__ float  g_V[(size_t)NN * 32];       // x@Wv+bv          [n][h*8+j]
__device__ __half g_M1[(size_t)NN * 512];     // hop-1 M (fp16), layout [n][h][j][i]
__device__ __half2 g_K1[(size_t)NN * 32];     // hop-1 K (fp16)  [n][lane]=(K[2l],K[2l+1])
__device__ float  g_hidden[(size_t)NN * 32];  // V*hw0 + g1*Hh1/Cc1
__device__ float  g_dinv[NN];
__device__ int    g_deg[NN];
__device__ int    g_off[NN + 1];
__device__ int    g_cursor[NN];
__device__ int    g_csr[NE];                  // source node per CSR slot (by dest)
__device__ int    g_part[NB];
__device__ int    g_pref[NB];
__device__ float  g_tm[512];                  // sum_n Kf⊗V, layout [h][j][i]
__device__ float  g_tk[64];                   // sum_n Kf
__device__ uint32_t g_Bf[64 * 8 * 32 * 2];    // Wi in tf32 mma-fragment layout (128 KB)

// ---------------- init ------------------------------------------------------
__global__ void k_zero() {
    int i = blockIdx.x * blockDim.x + threadIdx.x;
    if (i < NN)  g_deg[i] = 0;
    if (i < 512) g_tm[i] = 0.f;
    if (i < 64)  g_tk[i] = 0.f;
}

__global__ void k_deg(const int* __restrict__ ei) {
    int e = blockIdx.x * blockDim.x + threadIdx.x;
    if (e < NE) {
        int c = ei[NE + e];
        if (c >= 0 && c < NN) atomicAdd(&g_deg[c], 1);
    }
}

// ---------------- 3-phase coalesced scan ------------------------------------
__global__ void __launch_bounds__(1024) k_scan1() {   // grid NB: tile sums
    __shared__ int s[32];
    int b = blockIdx.x, t = threadIdx.x;
    int idx = b * 1024 + t;
    int v = (idx < NN) ? g_deg[idx] : 0;
#pragma unroll
    for (int o = 16; o; o >>= 1) v += __shfl_down_sync(0xffffffffu, v, o);
    if ((t & 31) == 0) s[t >> 5] = v;
    __syncthreads();
    if (t < 32) {
        int x = s[t];
#pragma unroll
        for (int o = 16; o; o >>= 1) x += __shfl_down_sync(0xffffffffu, x, o);
        if (t == 0) g_part[b] = x;
    }
}

__global__ void k_scan2() {   // 1 block, 64 threads: exclusive scan of NB partials
    __shared__ int sp[64];
    int t = threadIdx.x;
    int v = (t < NB) ? g_part[t] : 0;
    sp[t] = v;
    __syncthreads();
    for (int d = 1; d < 64; d <<= 1) {
        int x = (t >= d) ? sp[t - d] : 0;
        __syncthreads();
        sp[t] += x;
        __syncthreads();
    }
    if (t < NB) g_pref[t] = sp[t] - v;  // exclusive
}

__global__ void __launch_bounds__(1024) k_scan3() {   // grid NB: tile scan + writes
    __shared__ int s[1024];
    int b = blockIdx.x, t = threadIdx.x;
    int idx = b * 1024 + t;
    int d = (idx < NN) ? g_deg[idx] : 0;
    s[t] = d;
    __syncthreads();
    for (int o = 1; o < 1024; o <<= 1) {
        int x = (t >= o) ? s[t - o] : 0;
        __syncthreads();
        s[t] += x;
        __syncthreads();
    }
    if (idx < NN) {
        int excl = g_pref[b] + s[t] - d;
        g_off[idx] = excl;
        g_cursor[idx] = excl;
        g_dinv[idx] = (d > 0) ? 1.0f / (float)d : 0.0f;
    }
    if (b == NB - 1 && t == 0) g_off[NN] = NE;
}

__global__ void k_csr(const int* __restrict__ ei) {
    int e = blockIdx.x * blockDim.x + threadIdx.x;
    if (e < NE) {
        int c = ei[NE + e];
        int r = ei[e];
        if (c >= 0 && c < NN && r >= 0 && r < NN) {
            int p = atomicAdd(&g_cursor[c], 1);
            if (p >= 0 && p < NE) g_csr[p] = r;
        }
    }
}

// ---------------- tf32 helpers ----------------------------------------------
__device__ __forceinline__ uint32_t f2tf(float f) {
    uint32_t u;
    asm("cvt.rna.tf32.f32 %0, %1;" : "=r"(u) : "f"(f));
    return u;
}
__device__ __forceinline__ void mma_tf32(float& c0, float& c1, float& c2, float& c3,
                                         uint32_t a0, uint32_t a1, uint32_t a2, uint32_t a3,
                                         uint32_t b0, uint32_t b1) {
    asm volatile(
        "mma.sync.aligned.m16n8k8.row.col.f32.tf32.tf32.f32 "
        "{%0,%1,%2,%3}, {%4,%5,%6,%7}, {%8,%9}, {%0,%1,%2,%3};"
        : "+f"(c0), "+f"(c1), "+f"(c2), "+f"(c3)
        : "r"(a0), "r"(a1), "r"(a2), "r"(a3), "r"(b0), "r"(b1));
}

// ---------------- prep B: Wi -> tf32 fragment layout in gmem ----------------
// g_Bf[kk][nf][lane] = uint2 { B[k=kk*8+(l&3)][n=nf*8+(l>>2)], B[k+4][n] }
__global__ void k_prepB(const float* __restrict__ Wi) {
    int t = blockIdx.x * blockDim.x + threadIdx.x;
    if (t >= 64 * 8 * 32) return;
    int lane = t & 31;
    int nf = (t >> 5) & 7;
    int kk = t >> 8;
    int n = nf * 8 + (lane >> 2);
    int k0 = kk * 8 + (lane & 3);
    int k1 = k0 + 4;
    uint32_t b0 = (k0 < FF) ? f2tf(Wi[k0 * 64 + n]) : 0u;
    uint32_t b1 = (k1 < FF) ? f2tf(Wi[k1 * 64 + n]) : 0u;
    ((uint2*)g_Bf)[t] = make_uint2(b0, b1);
}

// ---------------- x = relu(node_feat @ Wi + bi), smem-free tf32 MMA ---------
__global__ void __launch_bounds__(256) k_gemm(const float* __restrict__ A,
                                              const float* __restrict__ Wi,
                                              const float* __restrict__ bi) {
    int tid = threadIdx.x;
    int l = tid & 31;
    int w = tid >> 5;
    int m0 = blockIdx.x * 128;
    int r0raw = m0 + w * 16 + (l >> 2);
    int r1raw = r0raw + 8;
    int r0c = (r0raw < NN) ? r0raw : NN - 1;
    int r1c = (r1raw < NN) ? r1raw : NN - 1;
    const float* a0p = A + (size_t)r0c * FF + (l & 3);
    const float* a1p = A + (size_t)r1c * FF + (l & 3);
    const uint2* bf = ((const uint2*)g_Bf) + l;

    float c_[8][4] = {};

#pragma unroll 4
    for (int kk = 0; kk < 62; kk++) {
        int k = kk * 8;
        uint32_t a0 = f2tf(a0p[k]);
        uint32_t a1 = f2tf(a1p[k]);
        uint32_t a2 = f2tf(a0p[k + 4]);
        uint32_t a3 = f2tf(a1p[k + 4]);
        const uint2* bb = bf + (size_t)(kk * 8) * 32;
#pragma unroll
        for (int nf = 0; nf < 8; nf++) {
            uint2 b = bb[(size_t)nf * 32];
            mma_tf32(c_[nf][0], c_[nf][1], c_[nf][2], c_[nf][3],
                     a0, a1, a2, a3, b.x, b.y);
        }
    }
    {   // kk = 62 tail: k = 496 + (l&3) < 500 valid; k+4 >= 500 -> zero
        int k = 62 * 8;
        uint32_t a0 = f2tf(a0p[k]);
        uint32_t a1 = f2tf(a1p[k]);
        const uint2* bb = bf + (size_t)(62 * 8) * 32;
#pragma unroll
        for (int nf = 0; nf < 8; nf++) {
            uint2 b = bb[(size_t)nf * 32];
            mma_tf32(c_[nf][0], c_[nf][1], c_[nf][2], c_[nf][3],
                     a0, a1, 0u, 0u, b.x, b.y);
        }
    }
#pragma unroll
    for (int nf = 0; nf < 8; nf++) {
        int col = nf * 8 + 2 * (l & 3);
        float b0v = bi[col], b1v = bi[col + 1];
        if (r0raw < NN) {
            float2 o;
            o.x = fmaxf(c_[nf][0] + b0v, 0.f);
            o.y = fmaxf(c_[nf][1] + b1v, 0.f);
            *(float2*)&g_x[(size_t)r0raw * 64 + col] = o;
        }
        if (r1raw < NN) {
            float2 o;
            o.x = fmaxf(c_[nf][2] + b0v, 0.f);
            o.y = fmaxf(c_[nf][3] + b1v, 0.f);
            *(float2*)&g_x[(size_t)r1raw * 64 + col] = o;
        }
    }
}

// ---------------- QKV: [50000,64] x [64,160] with fused 1+elu ---------------
__global__ void __launch_bounds__(256) k_qkv(const float* __restrict__ Wq, const float* __restrict__ bq,
                                             const float* __restrict__ Wk, const float* __restrict__ bk,
                                             const float* __restrict__ Wv, const float* __restrict__ bv) {
    __shared__ float Xs[64 * 65];  // [m][k], pad 65
    __shared__ float Ws[64 * 80];  // [k][c_local]
    __shared__ float bs[80];
    int tid = threadIdx.x;
    int m0 = blockIdx.x * 64;
#pragma unroll
    for (int r = 0; r < 16; r++) {
        int idx = r * 256 + tid;
        int k = idx & 63, m = idx >> 6;
        int row = m0 + m; if (row >= NN) row = NN - 1;
        Xs[m * 65 + k] = g_x[(long)row * 64 + k];
    }
    int msub = tid >> 4, nsub = tid & 15;
    for (int pass = 0; pass < 2; pass++) {
        int c0 = pass * 80;
#pragma unroll
        for (int r = 0; r < 20; r++) {
            int idx = r * 256 + tid;
            int k = idx / 80, cl = idx - k * 80;
            int c = c0 + cl;
            float wv;
            if (c < 64)       wv = Wq[k * 64 + c];
            else if (c < 128) wv = Wk[k * 64 + (c - 64)];
            else              wv = Wv[k * 32 + (c - 128)];
            Ws[k * 80 + cl] = wv;
        }
        if (tid < 80) {
            int c = c0 + tid;
            bs[tid] = (c < 64) ? bq[c] : (c < 128) ? bk[c - 64] : bv[c - 128];
        }
        __syncthreads();
        float acc[4][5] = {};
#pragma unroll
        for (int k = 0; k < 64; k++) {
            float a[4], b[5];
#pragma unroll
            for (int i = 0; i < 4; i++) a[i] = Xs[(msub * 4 + i) * 65 + k];
#pragma unroll
            for (int j = 0; j < 5; j++) b[j] = Ws[k * 80 + nsub + 16 * j];
#pragma unroll
            for (int i = 0; i < 4; i++)
#pragma unroll
                for (int j = 0; j < 5; j++) acc[i][j] = fmaf(a[i], b[j], acc[i][j]);
        }
#pragma unroll
        for (int i = 0; i < 4; i++) {
            int row = m0 + msub * 4 + i;
            if (row < NN) {
#pragma unroll
                for (int j = 0; j < 5; j++) {
                    int c = c0 + nsub + 16 * j;
                    float z = acc[i][j] + bs[nsub + 16 * j];
                    if (c < 128) {
                        z = (z > 0.f) ? (1.f + z) : __expf(z);  // 1 + elu
                        if (c < 64) g_Q[(long)row * 64 + c] = z;
                        else        g_K[(long)row * 64 + (c - 64)] = z;
                    } else {
                        g_V[(long)row * 32 + (c - 128)] = z;
                    }
                }
            }
        }
        __syncthreads();
    }
}

// ---------------- teleport sums: sum_n Kf, sum_n Kf⊗V -----------------------
__global__ void k_tele() {
    int gt = blockIdx.x * blockDim.x + threadIdx.x;
    int w = gt >> 5;
    int l = threadIdx.x & 31;
    int nw = (gridDim.x * blockDim.x) >> 5;
    int grp = l & ~7;
    float macc[16] = {};
    float2 kacc = make_float2(0.f, 0.f);
    for (int n = w; n < NN; n += nw) {
        float2 kf = ((const float2*)g_K)[n * 32 + l];
        float v = g_V[n * 32 + l];
        kacc.x += kf.x; kacc.y += kf.y;
#pragma unroll
        for (int i = 0; i < 16; i++) {
            float kfi = __shfl_sync(0xffffffffu, (i & 1) ? kf.y : kf.x, grp + (i >> 1));
            macc[i] = fmaf(kfi, v, macc[i]);
        }
    }
#pragma unroll
    for (int i = 0; i < 16; i++) atomicAdd(&g_tm[l * 16 + i], macc[i]);
    atomicAdd(&g_tk[2 * l], kacc.x);
    atomicAdd(&g_tk[2 * l + 1], kacc.y);
}

// ---------------- hop 1: build M1,K1 (fp16); hidden = V*hw0 + g1*Hh1/Cc1 ----
// warp per dest node; lane l: h=l>>3, i2=l&7. 4-edge unrolled, loads up front.
__global__ void __launch_bounds__(256) k_hop1(const float* __restrict__ hopwise,
                                              const float* __restrict__ headwise) {
    int w = (blockIdx.x * blockDim.x + threadIdx.x) >> 5;
    if (w >= NN) return;
    int n = w;
    int l = threadIdx.x & 31;
    int h = l >> 3;
    int i2 = l & 7;
    int grp = l & ~7;
    float ax[8] = {}, ay[8] = {};
    float2 kf1 = make_float2(0.f, 0.f);
    int e0 = g_off[n], e1 = g_off[n + 1];
    for (int eb = e0; eb < e1; eb += 32) {
        int m = e1 - eb; if (m > 32) m = 32;
        int   rl  = (eb + l < e1) ? g_csr[eb + l] : 0;
        float dil = (eb + l < e1) ? g_dinv[rl] : 0.f;
        int t = 0;
        for (; t + 3 < m; t += 4) {
            int   ra  = __shfl_sync(0xffffffffu, rl, t);
            int   rb  = __shfl_sync(0xffffffffu, rl, t + 1);
            int   rc  = __shfl_sync(0xffffffffu, rl, t + 2);
            int   rd  = __shfl_sync(0xffffffffu, rl, t + 3);
            float dia = __shfl_sync(0xffffffffu, dil, t);
            float dib = __shfl_sync(0xffffffffu, dil, t + 1);
            float dic = __shfl_sync(0xffffffffu, dil, t + 2);
            float did = __shfl_sync(0xffffffffu, dil, t + 3);
            // all 8 loads issued before any use (MLP 8)
            float2 kfa = ((const float2*)g_K)[ra * 32 + l];
            float2 kfb = ((const float2*)g_K)[rb * 32 + l];
            float2 kfc = ((const float2*)g_K)[rc * 32 + l];
            float2 kfd = ((const float2*)g_K)[rd * 32 + l];
            float  va  = g_V[ra * 32 + l];
            float  vb  = g_V[rb * 32 + l];
            float  vc  = g_V[rc * 32 + l];
            float  vd  = g_V[rd * 32 + l];
            float kxa = kfa.x * dia, kya = kfa.y * dia;
            float kxb = kfb.x * dib, kyb = kfb.y * dib;
            float kxc = kfc.x * dic, kyc = kfc.y * dic;
            float kxd = kfd.x * did, kyd = kfd.y * did;
            kf1.x += (kxa + kxb) + (kxc + kxd);
            kf1.y += (kya + kyb) + (kyc + kyd);
#pragma unroll
            for (int j = 0; j < 8; j++) {
                float vja = __shfl_sync(0xffffffffu, va, grp + j);
                float vjb = __shfl_sync(0xffffffffu, vb, grp + j);
                float vjc = __shfl_sync(0xffffffffu, vc, grp + j);
                float vjd = __shfl_sync(0xffffffffu, vd, grp + j);
                ax[j] = fmaf(kxa, vja, fmaf(kxb, vjb, fmaf(kxc, vjc, fmaf(kxd, vjd, ax[j]))));
                ay[j] = fmaf(kya, vja, fmaf(kyb, vjb, fmaf(kyc, vjc, fmaf(kyd, vjd, ay[j]))));
            }
        }
        for (; t < m; t++) {
            int   r  = __shfl_sync(0xffffffffu, rl, t);
            float di = __shfl_sync(0xffffffffu, dil, t);
            float2 kf = ((const float2*)g_K)[r * 32 + l];
            float  v  = g_V[r * 32 + l];
            float kx = kf.x * di, ky = kf.y * di;
            kf1.x += kx; kf1.y += ky;
#pragma unroll
            for (int j = 0; j < 8; j++) {
                float vj = __shfl_sync(0xffffffffu, v, grp + j);
                ax[j] = fmaf(kx, vj, ax[j]);
                ay[j] = fmaf(ky, vj, ay[j]);
            }
        }
    }
    // write M1 fp16: M1[n][h][j][i] at i = 2*i2, 2*i2+1
    {
        __half* base = &g_M1[(size_t)n * 512 + h * 128 + 2 * i2];
#pragma unroll
        for (int j = 0; j < 8; j++)
            *(__half2*)&base[j * 16] = __floats2half2_rn(ax[j], ay[j]);
        g_K1[n * 32 + l] = __floats2half2_rn(kf1.x, kf1.y);
    }
    // Hh1: p[j] = Q[h][2i2]*ax[j] + Q[h][2i2+1]*ay[j]; 3-round reduce-scatter
    float2 q2 = ((const float2*)g_Q)[n * 32 + l];
    float p[8];
#pragma unroll
    for (int j = 0; j < 8; j++) p[j] = fmaf(q2.x, ax[j], q2.y * ay[j]);
    int b0 = i2 & 1, b1 = (i2 >> 1) & 1, b2 = (i2 >> 2) & 1;
    float k0 = b0 ? p[1] : p[0], s0 = b0 ? p[0] : p[1];
    float k1 = b0 ? p[3] : p[2], s1 = b0 ? p[2] : p[3];
    float k2 = b0 ? p[5] : p[4], s2 = b0 ? p[4] : p[5];
    float k3 = b0 ? p[7] : p[6], s3 = b0 ? p[6] : p[7];
    k0 += __shfl_xor_sync(0xffffffffu, s0, 1);
    k1 += __shfl_xor_sync(0xffffffffu, s1, 1);
    k2 += __shfl_xor_sync(0xffffffffu, s2, 1);
    k3 += __shfl_xor_sync(0xffffffffu, s3, 1);
    float t0 = b1 ? k1 : k0, u0 = b1 ? k0 : k1;
    float t1 = b1 ? k3 : k2, u1 = b1 ? k2 : k3;
    t0 += __shfl_xor_sync(0xffffffffu, u0, 2);
    t1 += __shfl_xor_sync(0xffffffffu, u1, 2);
    float w0 = b2 ? t1 : t0, w1 = b2 ? t0 : t1;
    w0 += __shfl_xor_sync(0xffffffffu, w1, 4);   // hh[j = i2]
    float cp = q2.x * kf1.x + q2.y * kf1.y;
    cp += __shfl_xor_sync(0xffffffffu, cp, 1);
    cp += __shfl_xor_sync(0xffffffffu, cp, 2);
    cp += __shfl_xor_sync(0xffffffffu, cp, 4);
    float es = __expf(headwise[0]) + __expf(headwise[2]) + __expf(headwise[4]) + __expf(headwise[6]);
    float g1 = hopwise[1] * __expf(headwise[h * 2 + 0]) / es;
    float v0 = g_V[n * 32 + l];
    g_hidden[n * 32 + l] = v0 * hopwise[0] + g1 * w0 / (cp + CSTF);
}

// ---------------- hop-2 helper: Q . M1row (fp16 unpack + 2 fp32 chains) -----
__device__ __forceinline__ float dotQM(const float* __restrict__ q, uint4 u0, uint4 u1) {
    const __half2* h0 = (const __half2*)&u0;
    const __half2* h1 = (const __half2*)&u1;
    float2 f;
    f = __half22float2(h0[0]); float da = q[0] * f.x, db = q[1] * f.y;
    f = __half22float2(h0[1]); da = fmaf(q[2],  f.x, da); db = fmaf(q[3],  f.y, db);
    f = __half22float2(h0[2]); da = fmaf(q[4],  f.x, da); db = fmaf(q[5],  f.y, db);
    f = __half22float2(h0[3]); da = fmaf(q[6],  f.x, da); db = fmaf(q[7],  f.y, db);
    f = __half22float2(h1[0]); da = fmaf(q[8],  f.x, da); db = fmaf(q[9],  f.y, db);
    f = __half22float2(h1[1]); da = fmaf(q[10], f.x, da); db = fmaf(q[11], f.y, db);
    f = __half22float2(h1[2]); da = fmaf(q[12], f.x, da); db = fmaf(q[13], f.y, db);
    f = __half22float2(h1[3]); da = fmaf(q[14], f.x, da); db = fmaf(q[15], f.y, db);
    return da + db;
}

// ---------------- hop 2 + teleport + output projection ----------------------
// 4-edge unrolled: 8x LDG.128 + 4x LDG.32 issued before consumption (MLP 12).
__global__ void __launch_bounds__(256) k_hop2(const float* __restrict__ Wo, const float* __restrict__ bo,
                                              const float* __restrict__ hopwise,
                                              const float* __restrict__ headwise,
                                              const float* __restrict__ teleport,
                                              float* __restrict__ out) {
    int w = (blockIdx.x * blockDim.x + threadIdx.x) >> 5;
    if (w >= NN) return;
    int n = w;
    int l = threadIdx.x & 31;
    int h = l >> 3;
    float q[16];
    {
        const float4* qp = (const float4*)&g_Q[(long)n * 64 + h * 16];
        float4 a = qp[0], b = qp[1], c = qp[2], d = qp[3];
        q[0] = a.x; q[1] = a.y; q[2] = a.z; q[3] = a.w;
        q[4] = b.x; q[5] = b.y; q[6] = b.z; q[7] = b.w;
        q[8] = c.x; q[9] = c.y; q[10] = c.z; q[11] = c.w;
        q[12] = d.x; q[13] = d.y; q[14] = d.z; q[15] = d.w;
    }
    float2 qq = ((const float2*)g_Q)[n * 32 + l];
    float hacc0 = 0.f, hacc1 = 0.f, cacc0 = 0.f, cacc1 = 0.f;
    int e0 = g_off[n], e1 = g_off[n + 1];
    for (int eb = e0; eb < e1; eb += 32) {
        int m = e1 - eb; if (m > 32) m = 32;
        int   rl  = (eb + l < e1) ? g_csr[eb + l] : 0;
        float dil = (eb + l < e1) ? g_dinv[rl] : 0.f;
        int t = 0;
        for (; t + 3 < m; t += 4) {
            int   ra  = __shfl_sync(0xffffffffu, rl, t);
            int   rb  = __shfl_sync(0xffffffffu, rl, t + 1);
            int   rc  = __shfl_sync(0xffffffffu, rl, t + 2);
            int   rd  = __shfl_sync(0xffffffffu, rl, t + 3);
            float dia = __shfl_sync(0xffffffffu, dil, t);
            float dib = __shfl_sync(0xffffffffu, dil, t + 1);
            float dic = __shfl_sync(0xffffffffu, dil, t + 2);
            float did = __shfl_sync(0xffffffffu, dil, t + 3);
            // all 12 loads issued before consumption
            const uint4* pa = (const uint4*)&g_M1[(size_t)ra * 512 + l * 16];
            const uint4* pb = (const uint4*)&g_M1[(size_t)rb * 512 + l * 16];
            const uint4* pc = (const uint4*)&g_M1[(size_t)rc * 512 + l * 16];
            const uint4* pd = (const uint4*)&g_M1[(size_t)rd * 512 + l * 16];
            uint4 A0 = pa[0], A1 = pa[1];
            uint4 B0 = pb[0], B1 = pb[1];
            uint4 C0 = pc[0], C1 = pc[1];
            uint4 D0 = pd[0], D1 = pd[1];
            __half2 kha = g_K1[ra * 32 + l];
            __half2 khb = g_K1[rb * 32 + l];
            __half2 khc = g_K1[rc * 32 + l];
            __half2 khd = g_K1[rd * 32 + l];
            hacc0 = fmaf(dia, dotQM(q, A0, A1), hacc0);
            hacc1 = fmaf(dib, dotQM(q, B0, B1), hacc1);
            hacc0 = fmaf(dic, dotQM(q, C0, C1), hacc0);
            hacc1 = fmaf(did, dotQM(q, D0, D1), hacc1);
            float2 ka = __half22float2(kha), kb = __half22float2(khb);
            float2 kc = __half22float2(khc), kd = __half22float2(khd);
            cacc0 = fmaf(dia, qq.x * ka.x + qq.y * ka.y, cacc0);
            cacc1 = fmaf(dib, qq.x * kb.x + qq.y * kb.y, cacc1);
            cacc0 = fmaf(dic, qq.x * kc.x + qq.y * kc.y, cacc0);
            cacc1 = fmaf(did, qq.x * kd.x + qq.y * kd.y, cacc1);
        }
        for (; t < m; t++) {
            int   r  = __shfl_sync(0xffffffffu, rl, t);
            float di = __shfl_sync(0xffffffffu, dil, t);
            const uint4* mp = (const uint4*)&g_M1[(size_t)r * 512 + l * 16];
            uint4 u0 = mp[0], u1 = mp[1];
            __half2 kh = g_K1[r * 32 + l];
            hacc0 = fmaf(di, dotQM(q, u0, u1), hacc0);
            float2 kff = __half22float2(kh);
            cacc0 = fmaf(di, qq.x * kff.x + qq.y * kff.y, cacc0);
        }
    }
    float hacc = hacc0 + hacc1;
    float cacc = cacc0 + cacc1;
    cacc += __shfl_xor_sync(0xffffffffu, cacc, 1);
    cacc += __shfl_xor_sync(0xffffffffu, cacc, 2);
    cacc += __shfl_xor_sync(0xffffffffu, cacc, 4);
    float es = __expf(headwise[1]) + __expf(headwise[3]) + __expf(headwise[5]) + __expf(headwise[7]);
    float g2 = hopwise[2] * __expf(headwise[h * 2 + 1]) / es;
    float hid = g_hidden[n * 32 + l] + g2 * hacc / (cacc + CSTF);
    float tH = 0.f, tC = 0.f;
#pragma unroll
    for (int i = 0; i < 16; i++) {
        tH = fmaf(q[i], g_tm[l * 16 + i], tH);
        tC = fmaf(q[i], g_tk[h * 16 + i], tC);
    }
    const float invN = 1.0f / (float)NN;
    float tv = (tH * invN) / (tC * invN + CSTF);
    tv += __shfl_xor_sync(0xffffffffu, tv, 8);
    tv += __shfl_xor_sync(0xffffffffu, tv, 16);
    float p[8];
    {
        const float4* wp = (const float4*)&Wo[l * 8];
        float4 w0 = wp[0], w1 = wp[1];
        p[0] = hid * w0.x; p[1] = hid * w0.y; p[2] = hid * w0.z; p[3] = hid * w0.w;
        p[4] = hid * w1.x; p[5] = hid * w1.y; p[6] = hid * w1.z; p[7] = hid * w1.w;
    }
#pragma unroll
    for (int s = 1; s < 32; s <<= 1) {
#pragma unroll
        for (int c = 0; c < 8; c++) p[c] += __shfl_xor_sync(0xffffffffu, p[c], s);
    }
    float tvv[8];
#pragma unroll
    for (int c = 0; c < 8; c++) tvv[c] = __shfl_sync(0xffffffffu, tv, c);
    if (l == 0) {
        float tel = teleport[0];
        float4 b0 = *(const float4*)&bo[0];
        float4 b1 = *(const float4*)&bo[4];
        float4 o0, o1;
        o0.x = p[0] + b0.x + tel * tvv[0];
        o0.y = p[1] + b0.y + tel * tvv[1];
        o0.z = p[2] + b0.z + tel * tvv[2];
        o0.w = p[3] + b0.w + tel * tvv[3];
        o1.x = p[4] + b1.x + tel * tvv[4];
        o1.y = p[5] + b1.y + tel * tvv[5];
        o1.z = p[6] + b1.z + tel * tvv[6];
        o1.w = p[7] + b1.w + tel * tvv[7];
        ((float4*)out)[(long)n * 2 + 0] = o0;
        ((float4*)out)[(long)n * 2 + 1] = o1;
    }
}

// ---------------- launch ----------------------------------------------------
// Capture-legal fork-join (R9 pattern): sB joins ONLY via wait on ev0 recorded
// on the origin stream BEFORE any sB launch.
extern "C" void kernel_launch(void* const* d_in, const int* in_sizes, int n_in,
                              void* d_out, int out_size) {
    const float* node_feat = (const float*)d_in[0];
    const int*   ei        = (const int*)d_in[1];
    const float* Wi        = (const float*)d_in[2];
    const float* bi        = (const float*)d_in[3];
    const float* Wq        = (const float*)d_in[4];
    const float* bq        = (const float*)d_in[5];
    const float* Wk        = (const float*)d_in[6];
    const float* bk        = (const float*)d_in[7];
    const float* Wv        = (const float*)d_in[8];
    const float* bv        = (const float*)d_in[9];
    const float* Wo        = (const float*)d_in[10];
    const float* bo        = (const float*)d_in[11];
    const float* hopwise   = (const float*)d_in[12];
    const float* headwise  = (const float*)d_in[13];
    const float* teleport  = (const float*)d_in[14];
    float* out = (float*)d_out;

    static cudaStream_t sB = nullptr;
    static cudaEvent_t ev0 = nullptr, evTele = nullptr;
    if (sB == nullptr) {
        cudaStreamCreateWithFlags(&sB, cudaStreamNonBlocking);
        cudaEventCreateWithFlags(&ev0, cudaEventDisableTiming);
        cudaEventCreateWithFlags(&evTele, cudaEventDisableTiming);
    }

    // --- origin stream: capture root ---
    k_zero<<<(NN + 255) / 256, 256>>>();                 // issue 1
    cudaEventRecord(ev0, 0);
    cudaStreamWaitEvent(sB, ev0, 0);                     // sB joins the capture HERE
    // --- stream B: dense chain ---
    k_prepB<<<64, 256, 0, sB>>>(Wi);                     // issue 2
    k_deg<<<(NE + 255) / 256, 256>>>(ei);                // issue 3
    k_gemm<<<(NN + 127) / 128, 256, 0, sB>>>(node_feat, Wi, bi);   // issue 4 (profiled slot)
    k_scan1<<<NB, 1024>>>();                             // issue 5
    k_scan2<<<1, 64>>>();                                // issue 6
    k_scan3<<<NB, 1024>>>();                             // issue 7
    k_csr<<<(NE + 255) / 256, 256>>>(ei);                // issue 8
    k_qkv<<<(NN + 63) / 64, 256, 0, sB>>>(Wq, bq, Wk, bk, Wv, bv); // issue 9
    k_tele<<<128, 256, 0, sB>>>();                       // issue 10
    cudaEventRecord(evTele, sB);
    // --- join: hop1 needs csr chain (origin) + Q/K/V/tele (sB) ---
    cudaStreamWaitEvent(0, evTele, 0);
    k_hop1<<<(NN * 32 + 255) / 256, 256>>>(hopwise, headwise);     // issue 11
    k_hop2<<<(NN * 32 + 255) / 256, 256>>>(Wo, bo, hopwise, headwise, teleport, out); // issue 12
}

// round 12
// speedup vs baseline: 1.0675x; 1.0675x over previous
#include <cuda_runtime.h>
#include <cuda_fp16.h>
#include <cstdint>

#define NN   50000
#define NE   800000
#define FF   500
#define NB   49          // (NN+1023)/1024 scan tiles
#define CSTF 1e-5f

// ---------------- scratch (static device globals; no allocation) ------------
__device__ float  g_x[(size_t)NN * 64];       // relu(node_feat@Wi+bi)
__device__ float  g_Q[(size_t)NN * 64];       // 1+elu(x@Wq+bq)   [n][h*16+i]
__device__ float  g_K[(size_t)NN * 64];       // 1+elu(x@Wk+bk)   [n][h*16+i]
__device__ float  g_V[(size_t)NN * 32];       // x@Wv+bv          [n][h*8+j]
// M1 fp16, SPLIT layout per node (512 halves):
//   A-region halves [0,256):   lane chunk l at l*8,  content M1[h=l>>3][j=l&7][i=0..7]
//   B-region halves [256,512): lane chunk l at 256+l*8, content i=8..15
__device__ __half g_M1[(size_t)NN * 512];
__device__ __half2 g_K1[(size_t)NN * 32];     // hop-1 K (fp16)  [n][lane]=(K[2l],K[2l+1])
__device__ float  g_hidden[(size_t)NN * 32];  // V*hw0 + g1*Hh1/Cc1
__device__ float  g_dinv[NN];
__device__ int    g_deg[NN];
__device__ int    g_off[NN + 1];
__device__ int    g_cursor[NN];
__device__ int    g_csr[NE];                  // source node per CSR slot (by dest)
__device__ int    g_part[NB];
__device__ int    g_pref[NB];
__device__ float  g_tm[512];                  // sum_n Kf⊗V, layout [h][j][i]
__device__ float  g_tk[64];                   // sum_n Kf
__device__ uint32_t g_Bf[64 * 8 * 32 * 2];    // Wi in tf32 mma-fragment layout (128 KB)

// ---------------- init ------------------------------------------------------
__global__ void k_zero() {
    int i = blockIdx.x * blockDim.x + threadIdx.x;
    if (i < NN)  g_deg[i] = 0;
    if (i < 512) g_tm[i] = 0.f;
    if (i < 64)  g_tk[i] = 0.f;
}

__global__ void k_deg(const int* __restrict__ ei) {
    int e = blockIdx.x * blockDim.x + threadIdx.x;
    if (e < NE) {
        int c = ei[NE + e];
        if (c >= 0 && c < NN) atomicAdd(&g_deg[c], 1);
    }
}

// ---------------- 3-phase coalesced scan ------------------------------------
__global__ void __launch_bounds__(1024) k_scan1() {   // grid NB: tile sums
    __shared__ int s[32];
    int b = blockIdx.x, t = threadIdx.x;
    int idx = b * 1024 + t;
    int v = (idx < NN) ? g_deg[idx] : 0;
#pragma unroll
    for (int o = 16; o; o >>= 1) v += __shfl_down_sync(0xffffffffu, v, o);
    if ((t & 31) == 0) s[t >> 5] = v;
    __syncthreads();
    if (t < 32) {
        int x = s[t];
#pragma unroll
        for (int o = 16; o; o >>= 1) x += __shfl_down_sync(0xffffffffu, x, o);
        if (t == 0) g_part[b] = x;
    }
}

__global__ void k_scan2() {   // 1 block, 64 threads: exclusive scan of NB partials
    __shared__ int sp[64];
    int t = threadIdx.x;
    int v = (t < NB) ? g_part[t] : 0;
    sp[t] = v;
    __syncthreads();
    for (int d = 1; d < 64; d <<= 1) {
        int x = (t >= d) ? sp[t - d] : 0;
        __syncthreads();
        sp[t] += x;
        __syncthreads();
    }
    if (t < NB) g_pref[t] = sp[t] - v;  // exclusive
}

__global__ void __launch_bounds__(1024) k_scan3() {   // grid NB: tile scan + writes
    __shared__ int s[1024];
    int b = blockIdx.x, t = threadIdx.x;
    int idx = b * 1024 + t;
    int d = (idx < NN) ? g_deg[idx] : 0;
    s[t] = d;
    __syncthreads();
    for (int o = 1; o < 1024; o <<= 1) {
        int x = (t >= o) ? s[t - o] : 0;
        __syncthreads();
        s[t] += x;
        __syncthreads();
    }
    if (idx < NN) {
        int excl = g_pref[b] + s[t] - d;
        g_off[idx] = excl;
        g_cursor[idx] = excl;
        g_dinv[idx] = (d > 0) ? 1.0f / (float)d : 0.0f;
    }
    if (b == NB - 1 && t == 0) g_off[NN] = NE;
}

__global__ void k_csr(const int* __restrict__ ei) {
    int e = blockIdx.x * blockDim.x + threadIdx.x;
    if (e < NE) {
        int c = ei[NE + e];
        int r = ei[e];
        if (c >= 0 && c < NN && r >= 0 && r < NN) {
            int p = atomicAdd(&g_cursor[c], 1);
            if (p >= 0 && p < NE) g_csr[p] = r;
        }
    }
}

// ---------------- tf32 helpers ----------------------------------------------
__device__ __forceinline__ uint32_t f2tf(float f) {
    uint32_t u;
    asm("cvt.rna.tf32.f32 %0, %1;" : "=r"(u) : "f"(f));
    return u;
}
__device__ __forceinline__ void mma_tf32(float& c0, float& c1, float& c2, float& c3,
                                         uint32_t a0, uint32_t a1, uint32_t a2, uint32_t a3,
                                         uint32_t b0, uint32_t b1) {
    asm volatile(
        "mma.sync.aligned.m16n8k8.row.col.f32.tf32.tf32.f32 "
        "{%0,%1,%2,%3}, {%4,%5,%6,%7}, {%8,%9}, {%0,%1,%2,%3};"
        : "+f"(c0), "+f"(c1), "+f"(c2), "+f"(c3)
        : "r"(a0), "r"(a1), "r"(a2), "r"(a3), "r"(b0), "r"(b1));
}

// ---------------- prep B: Wi -> tf32 fragment layout in gmem ----------------
__global__ void k_prepB(const float* __restrict__ Wi) {
    int t = blockIdx.x * blockDim.x + threadIdx.x;
    if (t >= 64 * 8 * 32) return;
    int lane = t & 31;
    int nf = (t >> 5) & 7;
    int kk = t >> 8;
    int n = nf * 8 + (lane >> 2);
    int k0 = kk * 8 + (lane & 3);
    int k1 = k0 + 4;
    uint32_t b0 = (k0 < FF) ? f2tf(Wi[k0 * 64 + n]) : 0u;
    uint32_t b1 = (k1 < FF) ? f2tf(Wi[k1 * 64 + n]) : 0u;
    ((uint2*)g_Bf)[t] = make_uint2(b0, b1);
}

// ---------------- x = relu(node_feat @ Wi + bi), smem-free tf32 MMA ---------
__global__ void __launch_bounds__(256) k_gemm(const float* __restrict__ A,
                                              const float* __restrict__ Wi,
                                              const float* __restrict__ bi) {
    int tid = threadIdx.x;
    int l = tid & 31;
    int w = tid >> 5;
    int m0 = blockIdx.x * 128;
    int r0raw = m0 + w * 16 + (l >> 2);
    int r1raw = r0raw + 8;
    int r0c = (r0raw < NN) ? r0raw : NN - 1;
    int r1c = (r1raw < NN) ? r1raw : NN - 1;
    const float* a0p = A + (size_t)r0c * FF + (l & 3);
    const float* a1p = A + (size_t)r1c * FF + (l & 3);
    const uint2* bf = ((const uint2*)g_Bf) + l;

    float c_[8][4] = {};

#pragma unroll 4
    for (int kk = 0; kk < 62; kk++) {
        int k = kk * 8;
        uint32_t a0 = f2tf(a0p[k]);
        uint32_t a1 = f2tf(a1p[k]);
        uint32_t a2 = f2tf(a0p[k + 4]);
        uint32_t a3 = f2tf(a1p[k + 4]);
        const uint2* bb = bf + (size_t)(kk * 8) * 32;
#pragma unroll
        for (int nf = 0; nf < 8; nf++) {
            uint2 b = bb[(size_t)nf * 32];
            mma_tf32(c_[nf][0], c_[nf][1], c_[nf][2], c_[nf][3],
                     a0, a1, a2, a3, b.x, b.y);
        }
    }
    {   // kk = 62 tail
        int k = 62 * 8;
        uint32_t a0 = f2tf(a0p[k]);
        uint32_t a1 = f2tf(a1p[k]);
        const uint2* bb = bf + (size_t)(62 * 8) * 32;
#pragma unroll
        for (int nf = 0; nf < 8; nf++) {
            uint2 b = bb[(size_t)nf * 32];
            mma_tf32(c_[nf][0], c_[nf][1], c_[nf][2], c_[nf][3],
                     a0, a1, 0u, 0u, b.x, b.y);
        }
    }
#pragma unroll
    for (int nf = 0; nf < 8; nf++) {
        int col = nf * 8 + 2 * (l & 3);
        float b0v = bi[col], b1v = bi[col + 1];
        if (r0raw < NN) {
            float2 o;
            o.x = fmaxf(c_[nf][0] + b0v, 0.f);
            o.y = fmaxf(c_[nf][1] + b1v, 0.f);
            *(float2*)&g_x[(size_t)r0raw * 64 + col] = o;
        }
        if (r1raw < NN) {
            float2 o;
            o.x = fmaxf(c_[nf][2] + b0v, 0.f);
            o.y = fmaxf(c_[nf][3] + b1v, 0.f);
            *(float2*)&g_x[(size_t)r1raw * 64 + col] = o;
        }
    }
}

// ---------------- QKV: [50000,64] x [64,160] with fused 1+elu ---------------
__global__ void __launch_bounds__(256) k_qkv(const float* __restrict__ Wq, const float* __restrict__ bq,
                                             const float* __restrict__ Wk, const float* __restrict__ bk,
                                             const float* __restrict__ Wv, const float* __restrict__ bv) {
    __shared__ float Xs[64 * 65];  // [m][k], pad 65
    __shared__ float Ws[64 * 80];  // [k][c_local]
    __shared__ float bs[80];
    int tid = threadIdx.x;
    int m0 = blockIdx.x * 64;
#pragma unroll
    for (int r = 0; r < 16; r++) {
        int idx = r * 256 + tid;
        int k = idx & 63, m = idx >> 6;
        int row = m0 + m; if (row >= NN) row = NN - 1;
        Xs[m * 65 + k] = g_x[(long)row * 64 + k];
    }
    int msub = tid >> 4, nsub = tid & 15;
    for (int pass = 0; pass < 2; pass++) {
        int c0 = pass * 80;
#pragma unroll
        for (int r = 0; r < 20; r++) {
            int idx = r * 256 + tid;
            int k = idx / 80, cl = idx - k * 80;
            int c = c0 + cl;
            float wv;
            if (c < 64)       wv = Wq[k * 64 + c];
            else if (c < 128) wv = Wk[k * 64 + (c - 64)];
            else              wv = Wv[k * 32 + (c - 128)];
            Ws[k * 80 + cl] = wv;
        }
        if (tid < 80) {
            int c = c0 + tid;
            bs[tid] = (c < 64) ? bq[c] : (c < 128) ? bk[c - 64] : bv[c - 128];
        }
        __syncthreads();
        float acc[4][5] = {};
#pragma unroll
        for (int k = 0; k < 64; k++) {
            float a[4], b[5];
#pragma unroll
            for (int i = 0; i < 4; i++) a[i] = Xs[(msub * 4 + i) * 65 + k];
#pragma unroll
            for (int j = 0; j < 5; j++) b[j] = Ws[k * 80 + nsub + 16 * j];
#pragma unroll
            for (int i = 0; i < 4; i++)
#pragma unroll
                for (int j = 0; j < 5; j++) acc[i][j] = fmaf(a[i], b[j], acc[i][j]);
        }
#pragma unroll
        for (int i = 0; i < 4; i++) {
            int row = m0 + msub * 4 + i;
            if (row < NN) {
#pragma unroll
                for (int j = 0; j < 5; j++) {
                    int c = c0 + nsub + 16 * j;
                    float z = acc[i][j] + bs[nsub + 16 * j];
                    if (c < 128) {
                        z = (z > 0.f) ? (1.f + z) : __expf(z);  // 1 + elu
                        if (c < 64) g_Q[(long)row * 64 + c] = z;
                        else        g_K[(long)row * 64 + (c - 64)] = z;
                    } else {
                        g_V[(long)row * 32 + (c - 128)] = z;
                    }
                }
            }
        }
        __syncthreads();
    }
}

// ---------------- teleport sums: sum_n Kf, sum_n Kf⊗V -----------------------
__global__ void k_tele() {
    int gt = blockIdx.x * blockDim.x + threadIdx.x;
    int w = gt >> 5;
    int l = threadIdx.x & 31;
    int nw = (gridDim.x * blockDim.x) >> 5;
    int grp = l & ~7;
    float macc[16] = {};
    float2 kacc = make_float2(0.f, 0.f);
    for (int n = w; n < NN; n += nw) {
        float2 kf = ((const float2*)g_K)[n * 32 + l];
        float v = g_V[n * 32 + l];
        kacc.x += kf.x; kacc.y += kf.y;
#pragma unroll
        for (int i = 0; i < 16; i++) {
            float kfi = __shfl_sync(0xffffffffu, (i & 1) ? kf.y : kf.x, grp + (i >> 1));
            macc[i] = fmaf(kfi, v, macc[i]);
        }
    }
#pragma unroll
    for (int i = 0; i < 16; i++) atomicAdd(&g_tm[l * 16 + i], macc[i]);
    atomicAdd(&g_tk[2 * l], kacc.x);
    atomicAdd(&g_tk[2 * l + 1], kacc.y);
}

// ---------------- hop 1: build M1,K1 (fp16); hidden = V*hw0 + g1*Hh1/Cc1 ----
// warp per dest node; lane l: h=l>>3, i2=l&7. 4-edge unrolled, loads up front.
// M1 writes use the SPLIT layout: half2 (i=2*i2,2*i2+1) for target chunk (h,j)
// goes to region sel=(i2>=4), byte (h*8+j)*16 + (i2&3)*4 within the region.
__global__ void __launch_bounds__(256) k_hop1(const float* __restrict__ hopwise,
                                              const float* __restrict__ headwise) {
    int w = (blockIdx.x * blockDim.x + threadIdx.x) >> 5;
    if (w >= NN) return;
    int n = w;
    int l = threadIdx.x & 31;
    int h = l >> 3;
    int i2 = l & 7;
    int grp = l & ~7;
    float ax[8] = {}, ay[8] = {};
    float2 kf1 = make_float2(0.f, 0.f);
    int e0 = g_off[n], e1 = g_off[n + 1];
    for (int eb = e0; eb < e1; eb += 32) {
        int m = e1 - eb; if (m > 32) m = 32;
        int   rl  = (eb + l < e1) ? g_csr[eb + l] : 0;
        float dil = (eb + l < e1) ? g_dinv[rl] : 0.f;
        int t = 0;
        for (; t + 3 < m; t += 4) {
            int   ra  = __shfl_sync(0xffffffffu, rl, t);
            int   rb  = __shfl_sync(0xffffffffu, rl, t + 1);
            int   rc  = __shfl_sync(0xffffffffu, rl, t + 2);
            int   rd  = __shfl_sync(0xffffffffu, rl, t + 3);
            float dia = __shfl_sync(0xffffffffu, dil, t);
            float dib = __shfl_sync(0xffffffffu, dil, t + 1);
            float dic = __shfl_sync(0xffffffffu, dil, t + 2);
            float did = __shfl_sync(0xffffffffu, dil, t + 3);
            float2 kfa = ((const float2*)g_K)[ra * 32 + l];
            float2 kfb = ((const float2*)g_K)[rb * 32 + l];
            float2 kfc = ((const float2*)g_K)[rc * 32 + l];
            float2 kfd = ((const float2*)g_K)[rd * 32 + l];
            float  va  = g_V[ra * 32 + l];
            float  vb  = g_V[rb * 32 + l];
            float  vc  = g_V[rc * 32 + l];
            float  vd  = g_V[rd * 32 + l];
            float kxa = kfa.x * dia, kya = kfa.y * dia;
            float kxb = kfb.x * dib, kyb = kfb.y * dib;
            float kxc = kfc.x * dic, kyc = kfc.y * dic;
            float kxd = kfd.x * did, kyd = kfd.y * did;
            kf1.x += (kxa + kxb) + (kxc + kxd);
            kf1.y += (kya + kyb) + (kyc + kyd);
#pragma unroll
            for (int j = 0; j < 8; j++) {
                float vja = __shfl_sync(0xffffffffu, va, grp + j);
                float vjb = __shfl_sync(0xffffffffu, vb, grp + j);
                float vjc = __shfl_sync(0xffffffffu, vc, grp + j);
                float vjd = __shfl_sync(0xffffffffu, vd, grp + j);
                ax[j] = fmaf(kxa, vja, fmaf(kxb, vjb, fmaf(kxc, vjc, fmaf(kxd, vjd, ax[j]))));
                ay[j] = fmaf(kya, vja, fmaf(kyb, vjb, fmaf(kyc, vjc, fmaf(kyd, vjd, ay[j]))));
            }
        }
        for (; t < m; t++) {
            int   r  = __shfl_sync(0xffffffffu, rl, t);
            float di = __shfl_sync(0xffffffffu, dil, t);
            float2 kf = ((const float2*)g_K)[r * 32 + l];
            float  v  = g_V[r * 32 + l];
            float kx = kf.x * di, ky = kf.y * di;
            kf1.x += kx; kf1.y += ky;
#pragma unroll
            for (int j = 0; j < 8; j++) {
                float vj = __shfl_sync(0xffffffffu, v, grp + j);
                ax[j] = fmaf(kx, vj, ax[j]);
                ay[j] = fmaf(ky, vj, ay[j]);
            }
        }
    }
    // write M1 fp16 in SPLIT layout
    {
        // region: A (i<8) for i2<4, B (i>=8) for i2>=4
        __half* base = &g_M1[(size_t)n * 512 + ((i2 >= 4) ? 256 : 0) + (i2 & 3) * 2 + h * 64];
        // chunk (h,j) at half-offset (h*8+j)*8 within region; we pre-added h*64
#pragma unroll
        for (int j = 0; j < 8; j++)
            *(__half2*)&base[j * 8] = __floats2half2_rn(ax[j], ay[j]);
        g_K1[n * 32 + l] = __floats2half2_rn(kf1.x, kf1.y);
    }
    // Hh1: p[j] = Q[h][2i2]*ax[j] + Q[h][2i2+1]*ay[j]; 3-round reduce-scatter
    float2 q2 = ((const float2*)g_Q)[n * 32 + l];
    float p[8];
#pragma unroll
    for (int j = 0; j < 8; j++) p[j] = fmaf(q2.x, ax[j], q2.y * ay[j]);
    int b0 = i2 & 1, b1 = (i2 >> 1) & 1, b2 = (i2 >> 2) & 1;
    float k0 = b0 ? p[1] : p[0], s0 = b0 ? p[0] : p[1];
    float k1 = b0 ? p[3] : p[2], s1 = b0 ? p[2] : p[3];
    float k2 = b0 ? p[5] : p[4], s2 = b0 ? p[4] : p[5];
    float k3 = b0 ? p[7] : p[6], s3 = b0 ? p[6] : p[7];
    k0 += __shfl_xor_sync(0xffffffffu, s0, 1);
    k1 += __shfl_xor_sync(0xffffffffu, s1, 1);
    k2 += __shfl_xor_sync(0xffffffffu, s2, 1);
    k3 += __shfl_xor_sync(0xffffffffu, s3, 1);
    float t0 = b1 ? k1 : k0, u0 = b1 ? k0 : k1;
    float t1 = b1 ? k3 : k2, u1 = b1 ? k2 : k3;
    t0 += __shfl_xor_sync(0xffffffffu, u0, 2);
    t1 += __shfl_xor_sync(0xffffffffu, u1, 2);
    float w0 = b2 ? t1 : t0, w1 = b2 ? t0 : t1;
    w0 += __shfl_xor_sync(0xffffffffu, w1, 4);   // hh[j = i2]
    float cp = q2.x * kf1.x + q2.y * kf1.y;
    cp += __shfl_xor_sync(0xffffffffu, cp, 1);
    cp += __shfl_xor_sync(0xffffffffu, cp, 2);
    cp += __shfl_xor_sync(0xffffffffu, cp, 4);
    float es = __expf(headwise[0]) + __expf(headwise[2]) + __expf(headwise[4]) + __expf(headwise[6]);
    float g1 = hopwise[1] * __expf(headwise[h * 2 + 0]) / es;
    float v0 = g_V[n * 32 + l];
    g_hidden[n * 32 + l] = v0 * hopwise[0] + g1 * w0 / (cp + CSTF);
}

// ---------------- hop-2 helper: Q . M1chunk (u0 = i0..7, u1 = i8..15) -------
__device__ __forceinline__ float dotQM(const float* __restrict__ q, uint4 u0, uint4 u1) {
    const __half2* h0 = (const __half2*)&u0;
    const __half2* h1 = (const __half2*)&u1;
    float2 f;
    f = __half22float2(h0[0]); float da = q[0] * f.x, db = q[1] * f.y;
    f = __half22float2(h0[1]); da = fmaf(q[2],  f.x, da); db = fmaf(q[3],  f.y, db);
    f = __half22float2(h0[2]); da = fmaf(q[4],  f.x, da); db = fmaf(q[5],  f.y, db);
    f = __half22float2(h0[3]); da = fmaf(q[6],  f.x, da); db = fmaf(q[7],  f.y, db);
    f = __half22float2(h1[0]); da = fmaf(q[8],  f.x, da); db = fmaf(q[9],  f.y, db);
    f = __half22float2(h1[1]); da = fmaf(q[10], f.x, da); db = fmaf(q[11], f.y, db);
    f = __half22float2(h1[2]); da = fmaf(q[12], f.x, da); db = fmaf(q[13], f.y, db);
    f = __half22float2(h1[3]); da = fmaf(q[14], f.x, da); db = fmaf(q[15], f.y, db);
    return da + db;
}

// ---------------- hop 2 + teleport + output projection ----------------------
// Split M1 layout: lane l reads uint4 at n*512 + l*8 (A) and n*512+256+l*8 (B)
// -> both LDG.128s have CONSECUTIVE lane addresses (4 lines, full sectors).
__global__ void __launch_bounds__(256) k_hop2(const float* __restrict__ Wo, const float* __restrict__ bo,
                                              const float* __restrict__ hopwise,
                                              const float* __restrict__ headwise,
                                              const float* __restrict__ teleport,
                                              float* __restrict__ out) {
    int w = (blockIdx.x * blockDim.x + threadIdx.x) >> 5;
    if (w >= NN) return;
    int n = w;
    int l = threadIdx.x & 31;
    int h = l >> 3;
    float q[16];
    {
        const float4* qp = (const float4*)&g_Q[(long)n * 64 + h * 16];
        float4 a = qp[0], b = qp[1], c = qp[2], d = qp[3];
        q[0] = a.x; q[1] = a.y; q[2] = a.z; q[3] = a.w;
        q[4] = b.x; q[5] = b.y; q[6] = b.z; q[7] = b.w;
        q[8] = c.x; q[9] = c.y; q[10] = c.z; q[11] = c.w;
        q[12] = d.x; q[13] = d.y; q[14] = d.z; q[15] = d.w;
    }
    float2 qq = ((const float2*)g_Q)[n * 32 + l];
    float hacc0 = 0.f, hacc1 = 0.f, cacc0 = 0.f, cacc1 = 0.f;
    int e0 = g_off[n], e1 = g_off[n + 1];
    for (int eb = e0; eb < e1; eb += 32) {
        int m = e1 - eb; if (m > 32) m = 32;
        int   rl  = (eb + l < e1) ? g_csr[eb + l] : 0;
        float dil = (eb + l < e1) ? g_dinv[rl] : 0.f;
        int t = 0;
        for (; t + 3 < m; t += 4) {
            int   ra  = __shfl_sync(0xffffffffu, rl, t);
            int   rb  = __shfl_sync(0xffffffffu, rl, t + 1);
            int   rc  = __shfl_sync(0xffffffffu, rl, t + 2);
            int   rd  = __shfl_sync(0xffffffffu, rl, t + 3);
            float dia = __shfl_sync(0xffffffffu, dil, t);
            float dib = __shfl_sync(0xffffffffu, dil, t + 1);
            float dic = __shfl_sync(0xffffffffu, dil, t + 2);
            float did = __shfl_sync(0xffffffffu, dil, t + 3);
            uint4 A0 = *(const uint4*)&g_M1[(size_t)ra * 512 + l * 8];
            uint4 A1 = *(const uint4*)&g_M1[(size_t)ra * 512 + 256 + l * 8];
            uint4 B0 = *(const uint4*)&g_M1[(size_t)rb * 512 + l * 8];
            uint4 B1 = *(const uint4*)&g_M1[(size_t)rb * 512 + 256 + l * 8];
            uint4 C0 = *(const uint4*)&g_M1[(size_t)rc * 512 + l * 8];
            uint4 C1 = *(const uint4*)&g_M1[(size_t)rc * 512 + 256 + l * 8];
            uint4 D0 = *(const uint4*)&g_M1[(size_t)rd * 512 + l * 8];
            uint4 D1 = *(const uint4*)&g_M1[(size_t)rd * 512 + 256 + l * 8];
            __half2 kha = g_K1[ra * 32 + l];
            __half2 khb = g_K1[rb * 32 + l];
            __half2 khc = g_K1[rc * 32 + l];
            __half2 khd = g_K1[rd * 32 + l];
            hacc0 = fmaf(dia, dotQM(q, A0, A1), hacc0);
            hacc1 = fmaf(dib, dotQM(q, B0, B1), hacc1);
            hacc0 = fmaf(dic, dotQM(q, C0, C1), hacc0);
            hacc1 = fmaf(did, dotQM(q, D0, D1), hacc1);
            float2 ka = __half22float2(kha), kb = __half22float2(khb);
            float2 kc = __half22float2(khc), kd = __half22float2(khd);
            cacc0 = fmaf(dia, qq.x * ka.x + qq.y * ka.y, cacc0);
            cacc1 = fmaf(dib, qq.x * kb.x + qq.y * kb.y, cacc1);
            cacc0 = fmaf(dic, qq.x * kc.x + qq.y * kc.y, cacc0);
            cacc1 = fmaf(did, qq.x * kd.x + qq.y * kd.y, cacc1);
        }
        for (; t < m; t++) {
            int   r  = __shfl_sync(0xffffffffu, rl, t);
            float di = __shfl_sync(0xffffffffu, dil, t);
            uint4 u0 = *(const uint4*)&g_M1[(size_t)r * 512 + l * 8];
            uint4 u1 = *(const uint4*)&g_M1[(size_t)r * 512 + 256 + l * 8];
            __half2 kh = g_K1[r * 32 + l];
            hacc0 = fmaf(di, dotQM(q, u0, u1), hacc0);
            float2 kff = __half22float2(kh);
            cacc0 = fmaf(di, qq.x * kff.x + qq.y * kff.y, cacc0);
        }
    }
    float hacc = hacc0 + hacc1;
    float cacc = cacc0 + cacc1;
    cacc += __shfl_xor_sync(0xffffffffu, cacc, 1);
    cacc += __shfl_xor_sync(0xffffffffu, cacc, 2);
    cacc += __shfl_xor_sync(0xffffffffu, cacc, 4);
    float es = __expf(headwise[1]) + __expf(headwise[3]) + __expf(headwise[5]) + __expf(headwise[7]);
    float g2 = hopwise[2] * __expf(headwise[h * 2 + 1]) / es;
    float hid = g_hidden[n * 32 + l] + g2 * hacc / (cacc + CSTF);
    float tH = 0.f, tC = 0.f;
#pragma unroll
    for (int i = 0; i < 16; i++) {
        tH = fmaf(q[i], g_tm[l * 16 + i], tH);
        tC = fmaf(q[i], g_tk[h * 16 + i], tC);
    }
    const float invN = 1.0f / (float)NN;
    float tv = (tH * invN) / (tC * invN + CSTF);
    tv += __shfl_xor_sync(0xffffffffu, tv, 8);
    tv += __shfl_xor_sync(0xffffffffu, tv, 16);
    float p[8];
    {
        const float4* wp = (const float4*)&Wo[l * 8];
        float4 w0 = wp[0], w1 = wp[1];
        p[0] = hid * w0.x; p[1] = hid * w0.y; p[2] = hid * w0.z; p[3] = hid * w0.w;
        p[4] = hid * w1.x; p[5] = hid * w1.y; p[6] = hid * w1.z; p[7] = hid * w1.w;
    }
#pragma unroll
    for (int s = 1; s < 32; s <<= 1) {
#pragma unroll
        for (int c = 0; c < 8; c++) p[c] += __shfl_xor_sync(0xffffffffu, p[c], s);
    }
    float tvv[8];
#pragma unroll
    for (int c = 0; c < 8; c++) tvv[c] = __shfl_sync(0xffffffffu, tv, c);
    if (l == 0) {
        float tel = teleport[0];
        float4 b0 = *(const float4*)&bo[0];
        float4 b1 = *(const float4*)&bo[4];
        float4 o0, o1;
        o0.x = p[0] + b0.x + tel * tvv[0];
        o0.y = p[1] + b0.y + tel * tvv[1];
        o0.z = p[2] + b0.z + tel * tvv[2];
        o0.w = p[3] + b0.w + tel * tvv[3];
        o1.x = p[4] + b1.x + tel * tvv[4];
        o1.y = p[5] + b1.y + tel * tvv[5];
        o1.z = p[6] + b1.z + tel * tvv[6];
        o1.w = p[7] + b1.w + tel * tvv[7];
        ((float4*)out)[(long)n * 2 + 0] = o0;
        ((float4*)out)[(long)n * 2 + 1] = o1;
    }
}

// ---------------- launch ----------------------------------------------------
// Capture-legal fork-join. NEW: hop1 waits only evQkv (csr is earlier on the
// origin stream), so k_tele overlaps k_hop1; hop2 waits evTele.
extern "C" void kernel_launch(void* const* d_in, const int* in_sizes, int n_in,
                              void* d_out, int out_size) {
    const float* node_feat = (const float*)d_in[0];
    const int*   ei        = (const int*)d_in[1];
    const float* Wi        = (const float*)d_in[2];
    const float* bi        = (const float*)d_in[3];
    const float* Wq        = (const float*)d_in[4];
    const float* bq        = (const float*)d_in[5];
    const float* Wk        = (const float*)d_in[6];
    const float* bk        = (const float*)d_in[7];
    const float* Wv        = (const float*)d_in[8];
    const float* bv        = (const float*)d_in[9];
    const float* Wo        = (const float*)d_in[10];
    const float* bo        = (const float*)d_in[11];
    const float* hopwise   = (const float*)d_in[12];
    const float* headwise  = (const float*)d_in[13];
    const float* teleport  = (const float*)d_in[14];
    float* out = (float*)d_out;

    static cudaStream_t sB = nullptr;
    static cudaEvent_t ev0 = nullptr, evQkv = nullptr, evTele = nullptr;
    if (sB == nullptr) {
        cudaStreamCreateWithFlags(&sB, cudaStreamNonBlocking);
        cudaEventCreateWithFlags(&ev0, cudaEventDisableTiming);
        cudaEventCreateWithFlags(&evQkv, cudaEventDisableTiming);
        cudaEventCreateWithFlags(&evTele, cudaEventDisableTiming);
    }

    // --- origin stream: capture root ---
    k_zero<<<(NN + 255) / 256, 256>>>();                 // submit 1
    cudaEventRecord(ev0, 0);
    cudaStreamWaitEvent(sB, ev0, 0);                     // sB joins the capture HERE
    // --- stream B: dense chain ---
    k_prepB<<<64, 256, 0, sB>>>(Wi);                     // submit 2
    k_deg<<<(NE + 255) / 256, 256>>>(ei);                // submit 3
    k_gemm<<<(NN + 127) / 128, 256, 0, sB>>>(node_feat, Wi, bi);   // submit 4 (profiled slot)
    k_scan1<<<NB, 1024>>>();                             // submit 5
    k_scan2<<<1, 64>>>();                                // submit 6
    k_scan3<<<NB, 1024>>>();                             // submit 7
    k_csr<<<(NE + 255) / 256, 256>>>(ei);                // submit 8
    k_qkv<<<(NN + 63) / 64, 256, 0, sB>>>(Wq, bq, Wk, bk, Wv, bv); // submit 9
    cudaEventRecord(evQkv, sB);
    k_tele<<<128, 256, 0, sB>>>();                       // submit 10 (overlaps hop1)
    cudaEventRecord(evTele, sB);
    // --- join: hop1 needs csr chain (origin order) + Q/K/V ---
    cudaStreamWaitEvent(0, evQkv, 0);
    k_hop1<<<(NN * 32 + 255) / 256, 256>>>(hopwise, headwise);     // submit 11
    cudaStreamWaitEvent(0, evTele, 0);                   // hop2 additionally needs tele sums
    k_hop2<<<(NN * 32 + 255) / 256, 256>>>(Wo, bo, hopwise, headwise, teleport, out); // submit 12
}